// round 12
// baseline (speedup 1.0000x reference)
#include <cuda_runtime.h>
#include <cfloat>

#define NPTS  4096
#define MQ    1024
#define CCH   64
#define GRID  20
#define NCELL (GRID * GRID)
#define CAP   64        // pts/cell; lambda=10.24, overflow prob ~1e-30
#define NB    512       // blocks (co-resident: 512 <= 148*4)
#define QPB   2         // queries per block
#define LCAP  512       // candidate capacity per query (expect ~41)
#define MAR   0.0500010f

__device__ float2   g_xy[NCELL * CAP];     // cell-sorted coords
__device__ int      g_id [NCELL * CAP];    // cell-sorted point ids
__device__ int      g_cnt[2][NCELL];       // counts, double-buffered by parity
__device__ unsigned g_epoch;               // monotonic run counter
__device__ unsigned g_arrive;              // monotonic barrier ticket counter

__device__ __forceinline__ int cellof(float v) {
    int c = (int)(v * 20.0f);
    return min(GRID - 1, max(0, c));
}

__global__ __launch_bounds__(256, 4)
void maxpool_binned_kernel(const float* __restrict__ values,
                           const float* __restrict__ coords,
                           const float* __restrict__ qcoords,
                           float* __restrict__ out) {
    __shared__ int   s_par;
    __shared__ int   s_list[QPB][LCAP];
    __shared__ int   s_cnt[QPB];
    __shared__ float s_part[8][CCH];

    const int tid = threadIdx.x;
    const int bid = blockIdx.x;

    // Per-execution parity (replays are serialized, so all NB increments of
    // one run land in the same NB-group; wrap-safe since 2^32 % (2*NB) == 0).
    if (tid == 0) {
        unsigned e = atomicAdd(&g_epoch, 1u);
        s_par = (int)((e / NB) & 1u);
        s_cnt[0] = 0;
        s_cnt[1] = 0;
    }
    __syncthreads();
    const int par = s_par;

    // ---- Phase A: bin 8 points per block; zero the OTHER parity's counts
    // for the next execution (nobody reads that buffer this run).
    if (tid < 8) {
        int i = bid * 8 + tid;
        float2 c = ((const float2*)coords)[i];
        int cell = cellof(c.y) * GRID + cellof(c.x);
        int pos = atomicAdd(&g_cnt[par][cell], 1);
        if (pos < CAP) {
            g_xy[cell * CAP + pos] = c;
            g_id[cell * CAP + pos] = i;
        }
    }
    if (tid == 8 && bid < NCELL) g_cnt[par ^ 1][bid] = 0;

    // ---- Grid barrier (all NB CTAs co-resident by construction).
    __syncthreads();
    if (tid == 0) {
        __threadfence();
        unsigned t = atomicAdd(&g_arrive, 1u);
        unsigned target = ((t / NB) + 1u) * NB;
        while ((int)(*(volatile unsigned*)&g_arrive - target) < 0)
            __nanosleep(32);
    }
    __syncthreads();

    // ---- Phase B: 2 queries/block, 4 warps per query.
    const int lane = tid & 31;
    const int w    = tid >> 5;
    const int qs   = w >> 2;            // query slot 0/1
    const int wq   = w & 3;             // warp within query
    const int q    = bid * QPB + qs;

    const float2 qc = ((const float2*)qcoords)[q];
    const float qx = qc.x, qy = qc.y;

    // Candidate cell window (<=3x3); margin absorbs float rounding at cell
    // boundaries, the exact mask test decides membership.
    const int xlo = cellof(qx - MAR), xhi = cellof(qx + MAR);
    const int ylo = cellof(qy - MAR), yhi = cellof(qy + MAR);
    const int nx = xhi - xlo + 1;
    const int ncells = nx * (yhi - ylo + 1);

    // Bin-structure reads via __ldcg: L1 is not coherent across the grid
    // barrier; L2 is. (Atomics/stores from phase A live in L2.)
    for (int ci = wq; ci < ncells; ci += 4) {
        const int cell = (ylo + ci / nx) * GRID + (xlo + ci % nx);
        const int ccnt = min(__ldcg(&g_cnt[par][cell]), CAP);
        for (int base = 0; base < ccnt; base += 32) {
            const int j = base + lane;
            bool ok = false;
            int  id = 0;
            if (j < ccnt) {
                float2 c = __ldcg(&g_xy[cell * CAP + j]);
                id = __ldcg(&g_id[cell * CAP + j]);
                ok = (fabsf(qx - c.x) < 0.05f) & (fabsf(qy - c.y) < 0.05f);
            }
            if (ok) {
                int p = atomicAdd(&s_cnt[qs], 1);
                if (p < LCAP) s_list[qs][p] = id;
            }
        }
    }
    __syncthreads();

    const int lcnt = min(s_cnt[qs], LCAP);

    // ---- Gather-max: 4 warp-slices per query; lane owns channels
    // {2*lane, 2*lane+1} -> coalesced 256B float2 row per warp. Unroll-4 MLP.
    const float2* __restrict__ v2 = (const float2*)values;
    float m0 = -FLT_MAX, m1 = -FLT_MAX;

    int j = wq;
    for (; j + 16 <= lcnt; j += 16) {
        int i0 = s_list[qs][j +  0];
        int i1 = s_list[qs][j +  4];
        int i2 = s_list[qs][j +  8];
        int i3 = s_list[qs][j + 12];
        float2 a = v2[i0 * 32 + lane];
        float2 b = v2[i1 * 32 + lane];
        float2 c = v2[i2 * 32 + lane];
        float2 d = v2[i3 * 32 + lane];
        m0 = fmaxf(m0, fmaxf(fmaxf(a.x, b.x), fmaxf(c.x, d.x)));
        m1 = fmaxf(m1, fmaxf(fmaxf(a.y, b.y), fmaxf(c.y, d.y)));
    }
    for (; j < lcnt; j += 4) {
        float2 a = v2[s_list[qs][j] * 32 + lane];
        m0 = fmaxf(m0, a.x);
        m1 = fmaxf(m1, a.y);
    }

    s_part[w][2 * lane]     = m0;
    s_part[w][2 * lane + 1] = m1;
    __syncthreads();

    // ---- Final reduce: threads 0-127 cover both queries' 64 channels.
    if (tid < QPB * CCH) {
        const int qsel = tid >> 6;
        const int ch   = tid & (CCH - 1);
        float r = fmaxf(fmaxf(s_part[qsel * 4 + 0][ch], s_part[qsel * 4 + 1][ch]),
                        fmaxf(s_part[qsel * 4 + 2][ch], s_part[qsel * 4 + 3][ch]));
        out[(bid * QPB + qsel) * CCH + ch] = r;
    }
}

extern "C" void kernel_launch(void* const* d_in, const int* in_sizes, int n_in,
                              void* d_out, int out_size) {
    const float* values  = (const float*)d_in[0];   // [N, C] f32
    const float* coords  = (const float*)d_in[1];   // [N, 2] f32
    const float* qcoords = (const float*)d_in[2];   // [M, 2] f32
    float* out = (float*)d_out;                     // [M, C] f32

    maxpool_binned_kernel<<<NB, 256>>>(values, coords, qcoords, out);
}

// round 14
// speedup vs baseline: 1.4604x; 1.4604x over previous
#include <cuda_runtime.h>
#include <cfloat>

#define NPTS 4096
#define MQ   1024
#define CCH  64
#define QPB  2          // queries per CTA
#define NB   (MQ / QPB) // 512 CTAs -> exactly one wave at 4 CTAs/SM
#define LCAP 512        // candidate capacity (expect ~41, sigma ~6)

__global__ __launch_bounds__(256, 4)
void maxpool_fused_kernel(const float* __restrict__ values,
                          const float* __restrict__ coords,
                          const float* __restrict__ qcoords,
                          float* __restrict__ out) {
    __shared__ int   s_list[QPB][LCAP];
    __shared__ int   s_cnt[QPB];
    __shared__ float s_part[8][CCH];

    const int tid  = threadIdx.x;
    const int lane = tid & 31;
    const int w    = tid >> 5;          // warp 0..7
    const int qs   = w >> 2;            // query slot 0/1
    const int wq   = w & 3;             // warp within query 0..3
    const int tq   = (tid & 127);       // thread within query 0..127
    const int q    = blockIdx.x * QPB + qs;

    if (tid < QPB) s_cnt[tid] = 0;
    __syncthreads();

    const float2 qc = ((const float2*)qcoords)[q];
    const float qx = qc.x, qy = qc.y;

    // ---- Phase 1: branch-free scan. 128 threads per query; each thread
    // tests 32 points as 16 x LDG.128 (2 pts each). Results accumulate into
    // one 32-bit register mask via predicated LOP3 -- no branches, so loads
    // batch deeply for MLP. FABS folds into FMNMX source modifiers.
    const float4* __restrict__ c4 = (const float4*)coords;
    unsigned mmask = 0;
    #pragma unroll
    for (int it = 0; it < 16; it++) {
        float4 c = c4[it * 128 + tq];
        bool ok0 = fmaxf(fabsf(qx - c.x), fabsf(qy - c.y)) < 0.05f;
        bool ok1 = fmaxf(fabsf(qx - c.z), fabsf(qy - c.w)) < 0.05f;
        mmask |= (ok0 ? (1u << (2 * it)) : 0u);
        mmask |= (ok1 ? (2u << (2 * it)) : 0u);
    }

    // Push matches (expected 0.32/thread; ~73% of threads skip entirely).
    while (mmask) {
        int b = __ffs(mmask) - 1;
        mmask &= mmask - 1;
        int idx = 2 * ((b >> 1) * 128 + tq) + (b & 1);
        int p = atomicAdd(&s_cnt[qs], 1);
        if (p < LCAP) s_list[qs][p] = idx;
    }
    __syncthreads();
    const int cnt = min(s_cnt[qs], LCAP);

    // ---- Phase 2: gather-max. 4 warp-slices per query; lane owns channels
    // {2*lane, 2*lane+1} -> one coalesced 256B float2 row per warp. Unroll-4.
    const float2* __restrict__ v2 = (const float2*)values;
    float m0 = -FLT_MAX, m1 = -FLT_MAX;

    int j = wq;
    for (; j + 16 <= cnt; j += 16) {
        int i0 = s_list[qs][j +  0];
        int i1 = s_list[qs][j +  4];
        int i2 = s_list[qs][j +  8];
        int i3 = s_list[qs][j + 12];
        float2 a = v2[i0 * 32 + lane];
        float2 b = v2[i1 * 32 + lane];
        float2 c = v2[i2 * 32 + lane];
        float2 d = v2[i3 * 32 + lane];
        m0 = fmaxf(m0, fmaxf(fmaxf(a.x, b.x), fmaxf(c.x, d.x)));
        m1 = fmaxf(m1, fmaxf(fmaxf(a.y, b.y), fmaxf(c.y, d.y)));
    }
    for (; j < cnt; j += 4) {
        float2 a = v2[s_list[qs][j] * 32 + lane];
        m0 = fmaxf(m0, a.x);
        m1 = fmaxf(m1, a.y);
    }

    s_part[w][2 * lane]     = m0;
    s_part[w][2 * lane + 1] = m1;
    __syncthreads();

    // ---- Final reduce: threads 0-127 cover both queries' 64 channels.
    if (tid < QPB * CCH) {
        const int qsel = tid >> 6;
        const int ch   = tid & (CCH - 1);
        float r = fmaxf(fmaxf(s_part[qsel * 4 + 0][ch], s_part[qsel * 4 + 1][ch]),
                        fmaxf(s_part[qsel * 4 + 2][ch], s_part[qsel * 4 + 3][ch]));
        out[(blockIdx.x * QPB + qsel) * CCH + ch] = r;
    }
}

extern "C" void kernel_launch(void* const* d_in, const int* in_sizes, int n_in,
                              void* d_out, int out_size) {
    const float* values  = (const float*)d_in[0];   // [N, C] f32
    const float* coords  = (const float*)d_in[1];   // [N, 2] f32
    const float* qcoords = (const float*)d_in[2];   // [M, 2] f32
    float* out = (float*)d_out;                     // [M, C] f32

    maxpool_fused_kernel<<<NB, 256>>>(values, coords, qcoords, out);
}

// round 15
// speedup vs baseline: 1.5736x; 1.0775x over previous
#include <cuda_runtime.h>
#include <cfloat>

#define NPTS 4096
#define MQ   1024
#define CCH  64
#define QPB  2            // queries per CTA (merged scan)
#define NB   (MQ / QPB)   // 512 CTAs
#define LCAP 512          // per-query candidate capacity (expect ~41)

__global__ __launch_bounds__(256)
void maxpool_fused_kernel(const float* __restrict__ values,
                          const float* __restrict__ coords,
                          const float* __restrict__ qcoords,
                          float* __restrict__ out) {
    __shared__ int   s_list[QPB][LCAP];
    __shared__ int   s_cnt[QPB];
    __shared__ float s_part[8][CCH];

    const int tid  = threadIdx.x;
    const int lane = tid & 31;
    const int w    = tid >> 5;          // warp 0..7

    if (tid < QPB) s_cnt[tid] = 0;

    // Both queries of this CTA in one LDG.128 (rows 2b and 2b+1 contiguous).
    const float4 qq = ((const float4*)qcoords)[blockIdx.x];
    const float q0x = qq.x, q0y = qq.y, q1x = qq.z, q1y = qq.w;

    __syncthreads();

    // ---- Phase 1: merged scan. Each coord float4 (2 points) loaded ONCE and
    // tested against both queries. All 8 loads preloaded -> one exposed L1
    // latency. Mask: q0 in bits[0:16), q1 in bits[16:32), branch-free.
    const float4* __restrict__ c4 = (const float4*)coords;
    float4 cc[8];
    #pragma unroll
    for (int it = 0; it < 8; it++) cc[it] = c4[it * 256 + tid];

    unsigned mk = 0;
    #pragma unroll
    for (int it = 0; it < 8; it++) {
        float4 c = cc[it];
        bool a0 = fmaxf(fabsf(q0x - c.x), fabsf(q0y - c.y)) < 0.05f;
        bool a1 = fmaxf(fabsf(q0x - c.z), fabsf(q0y - c.w)) < 0.05f;
        bool b0 = fmaxf(fabsf(q1x - c.x), fabsf(q1y - c.y)) < 0.05f;
        bool b1 = fmaxf(fabsf(q1x - c.z), fabsf(q1y - c.w)) < 0.05f;
        mk |= (a0 ? (1u << (2 * it)) : 0u);
        mk |= (a1 ? (2u << (2 * it)) : 0u);
        mk |= (b0 ? (1u << (16 + 2 * it)) : 0u);
        mk |= (b1 ? (2u << (16 + 2 * it)) : 0u);
    }

    // ---- Warp-aggregated push: one packed scan, one shared atomic per warp
    // per query, then offset writes (no atomics, no per-match branching cost).
    unsigned m0 = mk & 0xFFFFu, m1 = mk >> 16;
    const int c0 = __popc(m0), c1 = __popc(m1);
    unsigned pk = (unsigned)c0 | ((unsigned)c1 << 16);
    #pragma unroll
    for (int d = 1; d < 32; d <<= 1) {
        unsigned n = __shfl_up_sync(0xFFFFFFFFu, pk, d);
        if (lane >= d) pk += n;
    }
    unsigned tot = __shfl_sync(0xFFFFFFFFu, pk, 31);
    int b0 = 0, b1 = 0;
    if (lane == 31) {
        b0 = atomicAdd(&s_cnt[0], (int)(tot & 0xFFFFu));
        b1 = atomicAdd(&s_cnt[1], (int)(tot >> 16));
    }
    b0 = __shfl_sync(0xFFFFFFFFu, b0, 31);
    b1 = __shfl_sync(0xFFFFFFFFu, b1, 31);
    int off0 = b0 + (int)(pk & 0xFFFFu) - c0;   // exclusive prefix
    int off1 = b1 + (int)(pk >> 16) - c1;

    while (m0) {
        int b = __ffs(m0) - 1; m0 &= m0 - 1;
        if (off0 < LCAP) s_list[0][off0] = 2 * ((b >> 1) * 256 + tid) + (b & 1);
        off0++;
    }
    while (m1) {
        int b = __ffs(m1) - 1; m1 &= m1 - 1;
        if (off1 < LCAP) s_list[1][off1] = 2 * ((b >> 1) * 256 + tid) + (b & 1);
        off1++;
    }
    __syncthreads();

    // ---- Phase 2: gather-max. 4 warp-slices per query; lane owns channels
    // {2*lane, 2*lane+1} -> coalesced 256B float2 rows. Unroll-4 MLP.
    const int qs  = w >> 2;              // query slot 0/1
    const int wq  = w & 3;               // warp within query
    const int cnt = min(s_cnt[qs], LCAP);

    const float2* __restrict__ v2 = (const float2*)values;
    float m0f = -FLT_MAX, m1f = -FLT_MAX;

    int j = wq;
    for (; j + 16 <= cnt; j += 16) {
        int i0 = s_list[qs][j +  0];
        int i1 = s_list[qs][j +  4];
        int i2 = s_list[qs][j +  8];
        int i3 = s_list[qs][j + 12];
        float2 a = v2[i0 * 32 + lane];
        float2 b = v2[i1 * 32 + lane];
        float2 c = v2[i2 * 32 + lane];
        float2 d = v2[i3 * 32 + lane];
        m0f = fmaxf(m0f, fmaxf(fmaxf(a.x, b.x), fmaxf(c.x, d.x)));
        m1f = fmaxf(m1f, fmaxf(fmaxf(a.y, b.y), fmaxf(c.y, d.y)));
    }
    for (; j < cnt; j += 4) {
        float2 a = v2[s_list[qs][j] * 32 + lane];
        m0f = fmaxf(m0f, a.x);
        m1f = fmaxf(m1f, a.y);
    }

    s_part[w][2 * lane]     = m0f;
    s_part[w][2 * lane + 1] = m1f;
    __syncthreads();

    // ---- Final reduce: threads 0-127 cover both queries' 64 channels.
    if (tid < QPB * CCH) {
        const int qsel = tid >> 6;
        const int ch   = tid & (CCH - 1);
        float r = fmaxf(fmaxf(s_part[qsel * 4 + 0][ch], s_part[qsel * 4 + 1][ch]),
                        fmaxf(s_part[qsel * 4 + 2][ch], s_part[qsel * 4 + 3][ch]));
        out[(blockIdx.x * QPB + qsel) * CCH + ch] = r;
    }
}

extern "C" void kernel_launch(void* const* d_in, const int* in_sizes, int n_in,
                              void* d_out, int out_size) {
    const float* values  = (const float*)d_in[0];   // [N, C] f32
    const float* coords  = (const float*)d_in[1];   // [N, 2] f32
    const float* qcoords = (const float*)d_in[2];   // [M, 2] f32
    float* out = (float*)d_out;                     // [M, C] f32

    maxpool_fused_kernel<<<NB, 256>>>(values, coords, qcoords, out);
}